// round 1
// baseline (speedup 1.0000x reference)
#include <cuda_runtime.h>
#include <cuda_bf16.h>

// Problem constants
#define NT   8            // num tasks
#define RK   48           // R*K = 16*3
#define DIM  768          // Cout*K = Cin*K
#define BATCH 32
#define CIN  256
#define COUT 256
#define HH   56
#define WW   56
#define HW   (HH*WW)      // 3136
#define WELEM (COUT*CIN*9)      // 589824 per-sample weight elems
#define SCALING 2.0f

// Scratch (device globals — no allocation allowed)
__device__ float g_stack[NT * DIM * DIM];          // 18.9 MB  [t][row*768+col]
__device__ float g_agg[(long)BATCH * WELEM];       // 75.5 MB  [b][o][ci][3][3]

// ---------------------------------------------------------------------------
// Kernel A: stack[t] = lora_B[t] (768x48) @ lora_A[t] (48x768)
// grid (48,48,8), block 256. 16x16 output tile, K=48 fully staged in smem.
// ---------------------------------------------------------------------------
__global__ void synth_stack_kernel(const float* __restrict__ lora_A,
                                   const float* __restrict__ lora_B) {
    int t    = blockIdx.z;
    int row0 = blockIdx.y * 16;
    int col0 = blockIdx.x * 16;
    __shared__ float Bs[16][RK];        // [r][k]
    __shared__ float As[RK][17];        // [k][c] (+pad)
    int tid = threadIdx.x;

    // load B tile: 16*48 = 768 elements
    for (int i = tid; i < 16 * RK; i += 256) {
        int r = i / RK, k = i % RK;
        Bs[r][k] = lora_B[((long)t * DIM + row0 + r) * RK + k];
    }
    // load A tile: 48*16 = 768 elements
    for (int i = tid; i < RK * 16; i += 256) {
        int k = i / 16, c = i % 16;
        As[k][c] = lora_A[((long)t * RK + k) * DIM + col0 + c];
    }
    __syncthreads();

    int r = tid >> 4, c = tid & 15;
    float acc = 0.f;
#pragma unroll
    for (int k = 0; k < RK; k++) acc += Bs[r][k] * As[k][c];
    g_stack[((long)t * DIM + row0 + r) * DIM + col0 + c] = acc;
}

// ---------------------------------------------------------------------------
// Kernel B: agg[b][f] = W[f] + SCALING * sum_t alphas[b][t] * stack[t][f]
// grid 2304, block 256 (589824 f-values). Each stack element read exactly once.
// ---------------------------------------------------------------------------
__global__ void build_agg_kernel(const float* __restrict__ alphas,
                                 const float* __restrict__ conv_w) {
    __shared__ float sal[BATCH * NT];   // 256 floats
    int tid = threadIdx.x;
    sal[tid] = alphas[tid];
    __syncthreads();

    long f = (long)blockIdx.x * 256 + tid;   // < 589824
    float s[NT];
#pragma unroll
    for (int t = 0; t < NT; t++) s[t] = g_stack[(long)t * WELEM + f];
    float wv = conv_w[f];

#pragma unroll 4
    for (int b = 0; b < BATCH; b++) {
        float a = wv;
#pragma unroll
        for (int t = 0; t < NT; t++) a += SCALING * sal[b * NT + t] * s[t];
        g_agg[(long)b * WELEM + f] = a;
    }
}

// ---------------------------------------------------------------------------
// Kernel C: per-sample direct 3x3 conv, pad 1.
// Block = (b, 32 out-ch, 4 rows x 56 cols). 256 threads.
// Thread: 2 out-ch x 14 cols. ci chunked by 16 through smem.
// grid (14, 8, 32)
// ---------------------------------------------------------------------------
#define BO   32   // out channels per block
#define CIT  16   // input channels per chunk
#define TR   4    // rows per block

__global__ __launch_bounds__(256, 2)
void conv_kernel(const float* __restrict__ x, float* __restrict__ out) {
    int b  = blockIdx.z;
    int o0 = blockIdx.y * BO;
    int y0 = blockIdx.x * TR;

    __shared__ float xs[CIT][TR + 2][58];   // rows y0-1..y0+4, cols -1..56
    __shared__ float ws[BO][CIT][9];

    int tid = threadIdx.x;
    int og  = tid >> 4;        // 0..15 -> out-ch pair (og*2, og*2+1)
    int sg  = tid & 15;
    int r   = sg >> 2;         // 0..3 row within tile
    int seg = sg & 3;          // 0..3 column segment
    int c0  = seg * 14;

    float acc[2][14];
#pragma unroll
    for (int e = 0; e < 2; e++)
#pragma unroll
        for (int p = 0; p < 14; p++) acc[e][p] = 0.f;

    const float* xb = x + (long)b * CIN * HW;
    const float* ab = g_agg + ((long)b * COUT + o0) * (CIN * 9);

    for (int ci0 = 0; ci0 < CIN; ci0 += CIT) {
        // stage x chunk: 16 ci x 6 rows x 58 cols = 5568 elems
        for (int i = tid; i < CIT * (TR + 2) * 58; i += 256) {
            int ci  = i / ((TR + 2) * 58);
            int rem = i % ((TR + 2) * 58);
            int rr  = rem / 58;
            int cc  = rem % 58;
            int y   = y0 + rr - 1;
            int xc  = cc - 1;
            float v = 0.f;
            if (y >= 0 && y < HH && xc >= 0 && xc < WW)
                v = xb[(long)(ci0 + ci) * HW + y * WW + xc];
            xs[ci][rr][cc] = v;
        }
        // stage weights: 32 o x 16 ci x 9 = 4608 elems
        for (int i = tid; i < BO * CIT * 9; i += 256) {
            int o   = i / (CIT * 9);
            int rem = i % (CIT * 9);
            int ci  = rem / 9;
            int q   = rem % 9;
            ws[o][ci][q] = ab[(long)o * (CIN * 9) + (ci0 + ci) * 9 + q];
        }
        __syncthreads();

#pragma unroll 1
        for (int ci = 0; ci < CIT; ci++) {
            // hoist 2x9 weights into registers
            float w0[9], w1[9];
#pragma unroll
            for (int q = 0; q < 9; q++) {
                w0[q] = ws[og * 2][ci][q];
                w1[q] = ws[og * 2 + 1][ci][q];
            }
#pragma unroll
            for (int kh = 0; kh < 3; kh++) {
                float xr[16];
#pragma unroll
                for (int j = 0; j < 16; j++) xr[j] = xs[ci][r + kh][c0 + j];
#pragma unroll
                for (int kw = 0; kw < 3; kw++) {
                    float a0 = w0[kh * 3 + kw];
                    float a1 = w1[kh * 3 + kw];
#pragma unroll
                    for (int p = 0; p < 14; p++) {
                        acc[0][p] += xr[p + kw] * a0;
                        acc[1][p] += xr[p + kw] * a1;
                    }
                }
            }
        }
        __syncthreads();
    }

#pragma unroll
    for (int e = 0; e < 2; e++) {
        int o = o0 + og * 2 + e;
        float* ob = out + ((long)b * COUT + o) * HW + (y0 + r) * WW + c0;
#pragma unroll
        for (int p = 0; p < 14; p++) ob[p] = acc[e][p];
    }
}

// ---------------------------------------------------------------------------
extern "C" void kernel_launch(void* const* d_in, const int* in_sizes, int n_in,
                              void* d_out, int out_size) {
    const float* x      = (const float*)d_in[0];  // [32,256,56,56]
    const float* alphas = (const float*)d_in[1];  // [32,8]
    const float* conv_w = (const float*)d_in[2];  // [256,256,3,3]
    const float* lora_A = (const float*)d_in[3];  // [8,48,768]
    const float* lora_B = (const float*)d_in[4];  // [8,768,48]
    float* out = (float*)d_out;                   // [32,256,56,56]

    // A: stack[t] = B_t @ A_t
    dim3 gA(DIM / 16, DIM / 16, NT);
    synth_stack_kernel<<<gA, 256>>>(lora_A, lora_B);

    // B: per-sample aggregated weights
    build_agg_kernel<<<WELEM / 256, 256>>>(alphas, conv_w);

    // C: per-sample conv
    dim3 gC(HH / TR, COUT / BO, BATCH);
    conv_kernel<<<gC, 256>>>(x, out);
}

// round 3
// speedup vs baseline: 2.9980x; 2.9980x over previous
#include <cuda_runtime.h>
#include <cstdint>

// ---------------- problem constants ----------------
#define NT    8
#define RK    48
#define DIM   768
#define BATCH 32
#define CIN   256
#define COUT  256
#define HH    56
#define WW    56
#define HW    3136
#define KTOT  2304            // Cin*9, reordered as tap*256+ci
#define WELEM (COUT*KTOT)     // 589824
#define SCALING 2.0f
#define PW    58
#define PPLANE (PW*PW)        // 3364

// ---------------- scratch (device globals) ----------------
__device__ float g_stack[NT * DIM * DIM];            // [t][f]  f = o*2304+ci*9+tap
__device__ float g_agg[(long)BATCH * WELEM];         // [b][o][tap*256+ci]
__device__ float g_xpad[(long)BATCH * CIN * PPLANE]; // [b][ci][58][58] zero-padded

__device__ __forceinline__ uint32_t f2tf(float f) {
    uint32_t r;
    asm("cvt.rna.tf32.f32 %0, %1;" : "=r"(r) : "f"(f));
    return r;
}

// ---------------------------------------------------------------------------
// Kernel P: zero-pad x -> g_xpad [b][ci][58][58]
// ---------------------------------------------------------------------------
__global__ void pad_kernel(const float* __restrict__ x) {
    long plane = blockIdx.x;               // b*256+ci
    const float* src = x + plane * HW;
    float* dst = g_xpad + plane * PPLANE;
    for (int i = threadIdx.x; i < PPLANE; i += 256) {
        int r = i / PW, c = i % PW;
        float v = 0.f;
        if (r >= 1 && r <= HH && c >= 1 && c <= WW) v = src[(r - 1) * WW + (c - 1)];
        dst[i] = v;
    }
}

// ---------------------------------------------------------------------------
// Kernel A: stack[t] = lora_B[t] (768x48) @ lora_A[t] (48x768)
// ---------------------------------------------------------------------------
__global__ void synth_stack_kernel(const float* __restrict__ lora_A,
                                   const float* __restrict__ lora_B) {
    int t    = blockIdx.z;
    int row0 = blockIdx.y * 16;
    int col0 = blockIdx.x * 16;
    __shared__ float Bs[16][RK];
    __shared__ float As[RK][17];
    int tid = threadIdx.x;
    for (int i = tid; i < 16 * RK; i += 256) {
        int r = i / RK, k = i % RK;
        Bs[r][k] = lora_B[((long)t * DIM + row0 + r) * RK + k];
    }
    for (int i = tid; i < RK * 16; i += 256) {
        int k = i / 16, c = i % 16;
        As[k][c] = lora_A[((long)t * RK + k) * DIM + col0 + c];
    }
    __syncthreads();
    int r = tid >> 4, c = tid & 15;
    float acc = 0.f;
#pragma unroll
    for (int k = 0; k < RK; k++) acc += Bs[r][k] * As[k][c];
    g_stack[((long)t * DIM + row0 + r) * DIM + col0 + c] = acc;
}

// ---------------------------------------------------------------------------
// Kernel B: agg[b][o][tap*256+ci] = W[f] + SCALING * sum_t alpha[b][t]*stack[t][f]
//           f = o*2304 + ci*9 + tap (original [o][ci][kh][kw] flat index)
// ---------------------------------------------------------------------------
__global__ void build_agg_kernel(const float* __restrict__ alphas,
                                 const float* __restrict__ conv_w) {
    __shared__ float sal[BATCH * NT];
    int tid = threadIdx.x;
    sal[tid] = alphas[tid];
    __syncthreads();

    long g = (long)blockIdx.x * 256 + tid;
    int o   = (int)(g / KTOT);
    int r2  = (int)(g % KTOT);
    int tap = r2 >> 8;
    int ci  = r2 & 255;
    long f = (long)o * KTOT + ci * 9 + tap;

    float s[NT];
#pragma unroll
    for (int t = 0; t < NT; t++) s[t] = g_stack[(long)t * WELEM + f];
    float wv = conv_w[f];

#pragma unroll 4
    for (int b = 0; b < BATCH; b++) {
        float a = wv;
#pragma unroll
        for (int t = 0; t < NT; t++) a += SCALING * sal[b * NT + t] * s[t];
        g_agg[(long)b * WELEM + g] = a;
    }
}

// ---------------------------------------------------------------------------
// Kernel C: tf32 mma.sync implicit-GEMM conv (baseline sm_103 HMMA path).
// CTA: M=128 (Cout half) x N=224 (4 image rows) x K=2304 in 72 chunks of 32.
// 512 threads = 16 warps (4m x 4n), warp tile 32x56.
// Double-buffered SMEM, register prefetch, one __syncthreads per chunk.
// ---------------------------------------------------------------------------
#define KC       32
#define NCHUNK   72
#define ASTRIDE  36                      // 128 rows x 36 words (padded)
#define BSTRIDE  232                     // 32 k-rows x 232 words (padded)
#define AU       (128 * ASTRIDE)         // 4608 words
#define BU       (KC * BSTRIDE)          // 7424 words
#define BUFU     (AU + BU)               // 12032 words
#define CONV_SMEM (2 * BUFU * 4)         // 96256 bytes

__global__ __launch_bounds__(512, 1)
void conv_mma_kernel(float* __restrict__ out) {
    extern __shared__ uint32_t sm[];

    const int tid  = threadIdx.x;
    const int lane = tid & 31;
    const int wid  = tid >> 5;
    const int wm   = wid >> 2;      // 0..3  -> m offset wm*32
    const int wn   = wid & 3;       // 0..3  -> n offset wn*56
    const int q    = lane >> 2;     // 0..7
    const int t4   = lane & 3;      // 0..3

    const int b  = blockIdx.z;
    const int mt = blockIdx.y;      // 0..1
    const int nt = blockIdx.x;      // 0..13, pixels [nt*224, nt*224+224)
    const int y0 = nt * 4;

    const float* agg_b = g_agg  + (long)b * WELEM + (long)(mt * 128) * KTOT;
    const float* xp_b  = g_xpad + (long)b * CIN * PPLANE;

    // prefetch thread mapping
    const int ar   = tid >> 2;          // A: row 0..127
    const int aseg = tid & 3;           // A: col segment (8 floats)
    const int bci  = tid >> 4;          // B: ci 0..31
    const int bpart= tid & 15;          // B: 16 parts x 14 px
    const int by   = bpart >> 2;        // row within tile (0..3)
    const int bx0  = (bpart & 3) * 14;  // col start

    float pa[8];
    float pb[14];

    // ---- prefetch chunk 0 ----
    {
        const float4* s = (const float4*)(agg_b + (long)ar * KTOT + aseg * 8);
        float4 v0 = s[0], v1 = s[1];
        pa[0]=v0.x; pa[1]=v0.y; pa[2]=v0.z; pa[3]=v0.w;
        pa[4]=v1.x; pa[5]=v1.y; pa[6]=v1.z; pa[7]=v1.w;
        // chunk 0: tap=0 -> kh=0, kw=0 ; ci0=0
        const float* p = xp_b + (long)bci * PPLANE + (y0 + by) * PW + bx0;
#pragma unroll
        for (int j = 0; j < 14; j++) pb[j] = p[j];
    }

    float acc[2][7][4];
#pragma unroll
    for (int i = 0; i < 2; i++)
#pragma unroll
        for (int j = 0; j < 7; j++)
#pragma unroll
            for (int e = 0; e < 4; e++) acc[i][j][e] = 0.f;

    for (int c = 0; c < NCHUNK; c++) {
        uint32_t* buf = sm + (c & 1) * BUFU;

        // ---- store prefetched chunk c into smem (as tf32 bits) ----
        {
            uint32_t* Adst = buf + ar * ASTRIDE + aseg * 8;
            uint32_t a0=f2tf(pa[0]),a1=f2tf(pa[1]),a2=f2tf(pa[2]),a3=f2tf(pa[3]);
            uint32_t a4=f2tf(pa[4]),a5=f2tf(pa[5]),a6=f2tf(pa[6]),a7=f2tf(pa[7]);
            asm volatile("st.shared.v4.b32 [%0], {%1,%2,%3,%4};"
                         :: "l"(Adst), "r"(a0),"r"(a1),"r"(a2),"r"(a3));
            asm volatile("st.shared.v4.b32 [%0], {%1,%2,%3,%4};"
                         :: "l"(Adst + 4), "r"(a4),"r"(a5),"r"(a6),"r"(a7));
            uint32_t* Bdst = buf + AU + bci * BSTRIDE + by * 56 + bx0;
#pragma unroll
            for (int j = 0; j < 14; j++) Bdst[j] = f2tf(pb[j]);
        }
        __syncthreads();

        // ---- prefetch chunk c+1 (clamped; result unused on last iter) ----
        {
            int cn  = (c + 1 < NCHUNK) ? (c + 1) : (NCHUNK - 1);
            int tap = cn >> 3;
            int ci0 = (cn & 7) * 32;
            int kh = tap / 3, kw = tap % 3;
            const float4* s = (const float4*)(agg_b + (long)ar * KTOT + cn * KC + aseg * 8);
            float4 v0 = s[0], v1 = s[1];
            pa[0]=v0.x; pa[1]=v0.y; pa[2]=v0.z; pa[3]=v0.w;
            pa[4]=v1.x; pa[5]=v1.y; pa[6]=v1.z; pa[7]=v1.w;
            const float* p = xp_b + (long)(ci0 + bci) * PPLANE + (y0 + by + kh) * PW + bx0 + kw;
#pragma unroll
            for (int j = 0; j < 14; j++) pb[j] = p[j];
        }

        // ---- compute chunk c ----
        const uint32_t* As = buf + wm * 32 * ASTRIDE;       // warp's 32 m-rows
        const uint32_t* Bs = buf + AU + wn * 56;            // warp's 56 n-cols
#pragma unroll
        for (int ks = 0; ks < 4; ks++) {
            const int kk = ks * 8;
            uint32_t af[2][4];
#pragma unroll
            for (int ms = 0; ms < 2; ms++) {
                const uint32_t* ap = As + (ms * 16 + q) * ASTRIDE + kk + t4;
                af[ms][0] = ap[0];
                af[ms][1] = ap[8 * ASTRIDE];
                af[ms][2] = ap[4];
                af[ms][3] = ap[8 * ASTRIDE + 4];
            }
            uint32_t bf[7][2];
#pragma unroll
            for (int ns = 0; ns < 7; ns++) {
                const uint32_t* bp = Bs + (kk + t4) * BSTRIDE + ns * 8 + q;
                bf[ns][0] = bp[0];
                bf[ns][1] = bp[4 * BSTRIDE];
            }
#pragma unroll
            for (int ms = 0; ms < 2; ms++)
#pragma unroll
                for (int ns = 0; ns < 7; ns++) {
                    asm volatile(
                        "mma.sync.aligned.m16n8k8.row.col.f32.tf32.tf32.f32 "
                        "{%0,%1,%2,%3}, {%4,%5,%6,%7}, {%8,%9}, {%0,%1,%2,%3};"
                        : "+f"(acc[ms][ns][0]), "+f"(acc[ms][ns][1]),
                          "+f"(acc[ms][ns][2]), "+f"(acc[ms][ns][3])
                        : "r"(af[ms][0]), "r"(af[ms][1]), "r"(af[ms][2]), "r"(af[ms][3]),
                          "r"(bf[ns][0]), "r"(bf[ns][1]));
                }
        }
        __syncthreads();
    }

    // ---- epilogue: direct global stores ----
    {
        const int mbase = mt * 128 + wm * 32;
        const int nbase = nt * 224 + wn * 56;
#pragma unroll
        for (int ms = 0; ms < 2; ms++) {
            int row0 = mbase + ms * 16 + q;
#pragma unroll
            for (int ns = 0; ns < 7; ns++) {
                int np = nbase + ns * 8 + t4 * 2;
                float2* d0 = (float2*)(out + ((long)(b * COUT + row0)) * HW + np);
                float2* d1 = (float2*)(out + ((long)(b * COUT + row0 + 8)) * HW + np);
                float2 v0 = make_float2(acc[ms][ns][0], acc[ms][ns][1]);
                float2 v1 = make_float2(acc[ms][ns][2], acc[ms][ns][3]);
                *d0 = v0;
                *d1 = v1;
            }
        }
    }
}

// ---------------------------------------------------------------------------
extern "C" void kernel_launch(void* const* d_in, const int* in_sizes, int n_in,
                              void* d_out, int out_size) {
    const float* x      = (const float*)d_in[0];
    const float* alphas = (const float*)d_in[1];
    const float* conv_w = (const float*)d_in[2];
    const float* lora_A = (const float*)d_in[3];
    const float* lora_B = (const float*)d_in[4];
    float* out = (float*)d_out;

    pad_kernel<<<BATCH * CIN, 256>>>(x);

    dim3 gA(DIM / 16, DIM / 16, NT);
    synth_stack_kernel<<<gA, 256>>>(lora_A, lora_B);

    build_agg_kernel<<<WELEM / 256, 256>>>(alphas, conv_w);

    cudaFuncSetAttribute(conv_mma_kernel,
                         cudaFuncAttributeMaxDynamicSharedMemorySize, CONV_SMEM);
    dim3 gC(14, 2, BATCH);
    conv_mma_kernel<<<gC, 512, CONV_SMEM>>>(out);
}

// round 4
// speedup vs baseline: 3.9764x; 1.3264x over previous
#include <cuda_runtime.h>
#include <cstdint>

// ---------------- problem constants ----------------
#define NT    8
#define RK    48
#define DIM   768
#define BATCH 32
#define CIN   256
#define COUT  256
#define HH    56
#define WW    56
#define HW    3136
#define KTOT  2304            // Cin*9, reordered as tap*256+ci
#define WELEM (COUT*KTOT)     // 589824
#define SCALING 2.0f
#define PW    60              // padded row width (16B-aligned rows)
#define PH    58
#define PPLANE (PH*PW)        // 3480

// ---------------- scratch (device globals) ----------------
__device__ float g_stack[NT * DIM * DIM];            // [t][f]  f = o*2304+ci*9+tap
__device__ float g_agg[(long)BATCH * WELEM];         // [b][o][tap*256+ci], tf32-rounded
__device__ float g_xpad[(long)BATCH * CIN * PPLANE]; // [b][ci][58][60], tf32-rounded, zero-pad

__device__ __forceinline__ uint32_t f2tf(float f) {
    uint32_t r;
    asm("cvt.rna.tf32.f32 %0, %1;" : "=r"(r) : "f"(f));
    return r;
}
__device__ __forceinline__ uint32_t smem_u32(const void* p) {
    uint32_t a;
    asm("{ .reg .u64 t; cvta.to.shared.u64 t, %1; cvt.u32.u64 %0, t; }" : "=r"(a) : "l"(p));
    return a;
}
__device__ __forceinline__ void cp16(uint32_t dst, const void* src) {
    asm volatile("cp.async.cg.shared.global [%0], [%1], 16;" :: "r"(dst), "l"(src));
}

// ---------------------------------------------------------------------------
// Kernel P: zero-pad x -> g_xpad [b][ci][58][60], values pre-rounded to tf32
// ---------------------------------------------------------------------------
__global__ void pad_kernel(const float* __restrict__ x) {
    long plane = blockIdx.x;               // b*256+ci
    const float* src = x + plane * HW;
    float* dst = g_xpad + plane * PPLANE;
    for (int i = threadIdx.x; i < PPLANE; i += 256) {
        int r = i / PW, c = i % PW;
        float v = 0.f;
        if (r >= 1 && r <= HH && c >= 1 && c <= WW) v = src[(r - 1) * WW + (c - 1)];
        dst[i] = __uint_as_float(f2tf(v));
    }
}

// ---------------------------------------------------------------------------
// Kernel A: stack[t] = lora_B[t] (768x48) @ lora_A[t] (48x768)
// Block: 32x128 output tile, K=48 staged. 256 threads, 16 outputs each.
// ---------------------------------------------------------------------------
__global__ void synth_stack_kernel(const float* __restrict__ lora_A,
                                   const float* __restrict__ lora_B) {
    int t    = blockIdx.z;
    int row0 = blockIdx.y * 32;
    int col0 = blockIdx.x * 128;
    __shared__ float Bs[32][RK + 1];
    __shared__ float As[RK][128];
    int tid = threadIdx.x;

    for (int i = tid; i < 32 * RK; i += 256) {
        int r = i / RK, k = i % RK;
        Bs[r][k] = lora_B[((long)t * DIM + row0 + r) * RK + k];
    }
    for (int i = tid; i < RK * 32; i += 256) {   // 1536 float4 loads
        int k = i / 32, c4 = i % 32;
        *(float4*)&As[k][c4 * 4] =
            *(const float4*)(lora_A + ((long)t * RK + k) * DIM + col0 + c4 * 4);
    }
    __syncthreads();

    int r  = tid >> 3;          // 0..31
    int c0 = (tid & 7) * 16;    // 0..112
    float acc[16];
#pragma unroll
    for (int j = 0; j < 16; j++) acc[j] = 0.f;
#pragma unroll
    for (int k = 0; k < RK; k++) {
        float bv = Bs[r][k];
#pragma unroll
        for (int j = 0; j < 16; j++) acc[j] += bv * As[k][c0 + j];
    }
    float* dst = &g_stack[((long)t * DIM + row0 + r) * DIM + col0 + c0];
#pragma unroll
    for (int j4 = 0; j4 < 4; j4++)
        *(float4*)(dst + j4 * 4) = make_float4(acc[j4*4], acc[j4*4+1], acc[j4*4+2], acc[j4*4+3]);
}

// ---------------------------------------------------------------------------
// Kernel B: agg[b][o][tap*256+ci] = tf32( W[f] + 2*sum_t alpha[b][t]*stack[t][f] )
//           f = o*2304 + ci*9 + tap
// ---------------------------------------------------------------------------
__global__ void build_agg_kernel(const float* __restrict__ alphas,
                                 const float* __restrict__ conv_w) {
    __shared__ float sal[BATCH * NT];
    int tid = threadIdx.x;
    sal[tid] = alphas[tid];
    __syncthreads();

    long g = (long)blockIdx.x * 256 + tid;
    int o   = (int)(g / KTOT);
    int r2  = (int)(g % KTOT);
    int tap = r2 >> 8;
    int ci  = r2 & 255;
    long f = (long)o * KTOT + ci * 9 + tap;

    float s[NT];
#pragma unroll
    for (int t = 0; t < NT; t++) s[t] = g_stack[(long)t * WELEM + f];
    float wv = conv_w[f];

#pragma unroll 4
    for (int b = 0; b < BATCH; b++) {
        float a = wv;
#pragma unroll
        for (int t = 0; t < NT; t++) a += SCALING * sal[b * NT + t] * s[t];
        g_agg[(long)b * WELEM + g] = __uint_as_float(f2tf(a));
    }
}

// ---------------------------------------------------------------------------
// Kernel C: tf32 mma.sync implicit-GEMM conv with 4-stage cp.async pipeline.
// CTA: M=128 x N=224 (4 rows x 56) x K=2304 in 72 chunks of 32.
// 512 threads, 16 warps (4m x 4n), warp tile 32x56.
// Operands pre-rounded to tf32 in prologue -> raw cp.async, zero cvt here.
// ---------------------------------------------------------------------------
#define KC        32
#define NCHUNK    72
#define ASTRIDE   36                  // A row stride (words): banks 4q+t4 all distinct
#define AWORDS    (128 * ASTRIDE)     // 4608
#define BCISTRIDE 248                 // B ci stride (words): 248 % 32 = 24 -> conflict-free
#define BWORDS    (KC * BCISTRIDE)    // 7936
#define STWORDS   (AWORDS + BWORDS)   // 12544
#define STAGES    4
#define CONV_SMEM (STAGES * STWORDS * 4)   // 200704 B

__global__ __launch_bounds__(512, 1)
void conv_mma_kernel(float* __restrict__ out) {
    extern __shared__ uint32_t sm[];
    const uint32_t smb = smem_u32(sm);

    const int tid  = threadIdx.x;
    const int lane = tid & 31;
    const int wid  = tid >> 5;
    const int wm   = wid >> 2;      // m offset wm*32
    const int wn   = wid & 3;       // n offset wn*56 -> image row wn
    const int q    = lane >> 2;     // 0..7
    const int t4   = lane & 3;      // 0..3

    const int b  = blockIdx.z;
    const int mt = blockIdx.y;      // 0..1
    const int nt = blockIdx.x;      // 0..13
    const int y0 = nt * 4;

    const float* agg_b = g_agg  + (long)b * WELEM + (long)(mt * 128) * KTOT;
    const float* xp_b  = g_xpad + (long)b * CIN * PPLANE;

    // staging thread mapping
    const int am   = tid >> 3;          // A row 0..63 (x2 iters)
    const int aseg = tid & 7;           // A 16B segment
    const int be   = tid % 15;          // B 16B segment within 60-float row
    const int br   = tid / 15;          // B row id (x~4 iters): ci = br>>2, yy = br&3

    // issue one K-chunk's cp.async loads into stage buffer
    auto issue = [&](int c, int buf) {
        uint32_t sa = smb + buf * (STWORDS * 4);
        // A: 128 rows x 32 words = 1024 x 16B
#pragma unroll
        for (int j = 0; j < 2; j++) {
            int m = am + j * 64;
            cp16(sa + (m * ASTRIDE + aseg * 4) * 4,
                 agg_b + (long)m * KTOT + c * KC + aseg * 4);
        }
        // B: 32 ci x 4 rows x 60 words = 1920 x 16B
        int tap = c >> 3;
        int ci0 = (c & 7) * 32;
        int kh  = tap / 3;
        uint32_t bbase = sa + AWORDS * 4;
        const float* gsrc = xp_b + (long)ci0 * PPLANE + (y0 + kh) * PW;
#pragma unroll
        for (int j = 0; j < 4; j++) {
            int idx = tid + j * 512;
            if (idx < 1920) {
                int e = idx % 15, r = idx / 15;
                int ci = r >> 2, yy = r & 3;
                cp16(bbase + (ci * BCISTRIDE + yy * PW + e * 4) * 4,
                     gsrc + (long)ci * PPLANE + yy * PW + e * 4);
            }
        }
        asm volatile("cp.async.commit_group;" ::: "memory");
    };

    // prologue: fill 3 stages
    issue(0, 0);
    issue(1, 1);
    issue(2, 2);

    float acc[2][7][4];
#pragma unroll
    for (int i = 0; i < 2; i++)
#pragma unroll
        for (int j = 0; j < 7; j++)
#pragma unroll
            for (int e = 0; e < 4; e++) acc[i][j][e] = 0.f;

    for (int c = 0; c < NCHUNK; c++) {
        asm volatile("cp.async.wait_group 2;" ::: "memory");
        __syncthreads();

        int buf = c & 3;

        // issue stage c+3 (its buffer was last consumed at chunk c-1)
        if (c + 3 < NCHUNK) issue(c + 3, (c + 3) & 3);
        else asm volatile("cp.async.commit_group;" ::: "memory");

        // ---- compute chunk c ----
        const int kw = (c >> 3) % 3;
        const uint32_t* As = sm + buf * STWORDS + wm * 32 * ASTRIDE;
        const uint32_t* Bs = sm + buf * STWORDS + AWORDS + wn * PW + kw;

#pragma unroll
        for (int ks = 0; ks < 4; ks++) {
            const int kk = ks * 8;
            uint32_t af[2][4];
#pragma unroll
            for (int ms = 0; ms < 2; ms++) {
                const uint32_t* ap = As + (ms * 16 + q) * ASTRIDE + kk + t4;
                af[ms][0] = ap[0];
                af[ms][1] = ap[8 * ASTRIDE];
                af[ms][2] = ap[4];
                af[ms][3] = ap[8 * ASTRIDE + 4];
            }
            uint32_t bf[7][2];
#pragma unroll
            for (int ns = 0; ns < 7; ns++) {
                const uint32_t* bp = Bs + (kk + t4) * BCISTRIDE + ns * 8 + q;
                bf[ns][0] = bp[0];
                bf[ns][1] = bp[4 * BCISTRIDE];
            }
#pragma unroll
            for (int ms = 0; ms < 2; ms++)
#pragma unroll
                for (int ns = 0; ns < 7; ns++) {
                    asm volatile(
                        "mma.sync.aligned.m16n8k8.row.col.f32.tf32.tf32.f32 "
                        "{%0,%1,%2,%3}, {%4,%5,%6,%7}, {%8,%9}, {%0,%1,%2,%3};"
                        : "+f"(acc[ms][ns][0]), "+f"(acc[ms][ns][1]),
                          "+f"(acc[ms][ns][2]), "+f"(acc[ms][ns][3])
                        : "r"(af[ms][0]), "r"(af[ms][1]), "r"(af[ms][2]), "r"(af[ms][3]),
                          "r"(bf[ns][0]), "r"(bf[ns][1]));
                }
        }
        __syncthreads();
    }

    // ---- epilogue: direct global stores ----
    {
        const int mbase = mt * 128 + wm * 32;
        const int nbase = nt * 224 + wn * 56;
#pragma unroll
        for (int ms = 0; ms < 2; ms++) {
            int row0 = mbase + ms * 16 + q;
#pragma unroll
            for (int ns = 0; ns < 7; ns++) {
                int np = nbase + ns * 8 + t4 * 2;
                *(float2*)(out + ((long)(b * COUT + row0)) * HW + np) =
                    make_float2(acc[ms][ns][0], acc[ms][ns][1]);
                *(float2*)(out + ((long)(b * COUT + row0 + 8)) * HW + np) =
                    make_float2(acc[ms][ns][2], acc[ms][ns][3]);
            }
        }
    }
}

// ---------------------------------------------------------------------------
extern "C" void kernel_launch(void* const* d_in, const int* in_sizes, int n_in,
                              void* d_out, int out_size) {
    const float* x      = (const float*)d_in[0];
    const float* alphas = (const float*)d_in[1];
    const float* conv_w = (const float*)d_in[2];
    const float* lora_A = (const float*)d_in[3];
    const float* lora_B = (const float*)d_in[4];
    float* out = (float*)d_out;

    pad_kernel<<<BATCH * CIN, 256>>>(x);

    dim3 gA(DIM / 128, DIM / 32, NT);
    synth_stack_kernel<<<gA, 256>>>(lora_A, lora_B);

    build_agg_kernel<<<WELEM / 256, 256>>>(alphas, conv_w);

    cudaFuncSetAttribute(conv_mma_kernel,
                         cudaFuncAttributeMaxDynamicSharedMemorySize, CONV_SMEM);
    dim3 gC(14, 2, BATCH);
    conv_mma_kernel<<<gC, 512, CONV_SMEM>>>(out);
}

// round 5
// speedup vs baseline: 7.0556x; 1.7744x over previous
#include <cuda_runtime.h>
#include <cuda_fp16.h>
#include <cstdint>

// ---------------- problem constants ----------------
#define NT    8
#define RK    48
#define DIM   768
#define BATCH 32
#define CIN   256
#define COUT  256
#define HH    56
#define WW    56
#define HW    3136
#define KTOT  2304            // Cin*9, reordered as tap*256+ci
#define WELEM (COUT*KTOT)     // 589824
#define SCALING 2.0f
#define PWH   64              // padded row width in halves (128B rows)
#define PH    58
#define PPLANE (PH*PWH)       // 3712

// ---------------- scratch (device globals) ----------------
__device__ float  g_stack[NT * DIM * DIM];                 // [t][f], f = o*2304+ci*9+tap
__device__ __half g_agg[(long)BATCH * WELEM];              // [b][o][tap*256+ci], fp16
__device__ __half g_xpad[3L * BATCH * CIN * PPLANE];       // [kw][b][ci][58][64], fp16, shifted

__device__ __forceinline__ uint32_t smem_u32(const void* p) {
    uint32_t a;
    asm("{ .reg .u64 t; cvta.to.shared.u64 t, %1; cvt.u32.u64 %0, t; }" : "=r"(a) : "l"(p));
    return a;
}
__device__ __forceinline__ void cp16(uint32_t dst, const void* src) {
    asm volatile("cp.async.cg.shared.global [%0], [%1], 16;" :: "r"(dst), "l"(src));
}

// ---------------------------------------------------------------------------
// Kernel P: 3 kw-shifted zero-padded fp16 copies of x.
// copy[kw][ci][y'][xx'] = x[ci][y'-1][xx'+kw-1] (0 outside), xx' in 0..63
// ---------------------------------------------------------------------------
__global__ void pad_kernel(const float* __restrict__ x) {
    int plane = blockIdx.x;                 // b*256+ci
    const float* src = x + (long)plane * HW;
#pragma unroll
    for (int kw = 0; kw < 3; kw++) {
        __half* dst = g_xpad + ((long)kw * BATCH * CIN + plane) * PPLANE;
        for (int i = threadIdx.x; i < PPLANE / 2; i += 256) {
            int idx = i * 2;
            int y = idx / PWH, x0 = idx % PWH;
            float v0 = 0.f, v1 = 0.f;
            if (y >= 1 && y <= HH) {
                const float* row = src + (y - 1) * WW;
                int xc = x0 + kw - 1;
                if (xc >= 0 && xc < WW) v0 = row[xc];
                if (xc + 1 >= 0 && xc + 1 < WW) v1 = row[xc + 1];
            }
            *(__half2*)(dst + idx) = __floats2half2_rn(v0, v1);
        }
    }
}

// ---------------------------------------------------------------------------
// Kernel A: stack[t] = lora_B[t] (768x48) @ lora_A[t] (48x768)
// ---------------------------------------------------------------------------
__global__ void synth_stack_kernel(const float* __restrict__ lora_A,
                                   const float* __restrict__ lora_B) {
    int t    = blockIdx.z;
    int row0 = blockIdx.y * 32;
    int col0 = blockIdx.x * 128;
    __shared__ float Bs[32][RK + 1];
    __shared__ float As[RK][128];
    int tid = threadIdx.x;

    for (int i = tid; i < 32 * RK; i += 256) {
        int r = i / RK, k = i % RK;
        Bs[r][k] = lora_B[((long)t * DIM + row0 + r) * RK + k];
    }
    for (int i = tid; i < RK * 32; i += 256) {
        int k = i / 32, c4 = i % 32;
        *(float4*)&As[k][c4 * 4] =
            *(const float4*)(lora_A + ((long)t * RK + k) * DIM + col0 + c4 * 4);
    }
    __syncthreads();

    int r  = tid >> 3;
    int c0 = (tid & 7) * 16;
    float acc[16];
#pragma unroll
    for (int j = 0; j < 16; j++) acc[j] = 0.f;
#pragma unroll
    for (int k = 0; k < RK; k++) {
        float bv = Bs[r][k];
#pragma unroll
        for (int j = 0; j < 16; j++) acc[j] += bv * As[k][c0 + j];
    }
    float* dst = &g_stack[((long)t * DIM + row0 + r) * DIM + col0 + c0];
#pragma unroll
    for (int j4 = 0; j4 < 4; j4++)
        *(float4*)(dst + j4 * 4) = make_float4(acc[j4*4], acc[j4*4+1], acc[j4*4+2], acc[j4*4+3]);
}

// ---------------------------------------------------------------------------
// Kernel B: agg fp16, reordered g = o*2304 + tap*256 + ci
//           f = o*2304 + ci*9 + tap. Each thread: 2 consecutive g (half2 store)
// ---------------------------------------------------------------------------
__global__ void build_agg_kernel(const float* __restrict__ alphas,
                                 const float* __restrict__ conv_w) {
    __shared__ float sal[BATCH * NT];
    int tid = threadIdx.x;
    sal[tid] = alphas[tid];
    __syncthreads();

    long g0 = ((long)blockIdx.x * 256 + tid) * 2;
    int o   = (int)(g0 / KTOT);
    int r2  = (int)(g0 % KTOT);
    int tap = r2 >> 8;
    int ci  = r2 & 255;
    long f0 = (long)o * KTOT + ci * 9 + tap;
    long f1 = f0 + 9;

    float s0[NT], s1[NT];
#pragma unroll
    for (int t = 0; t < NT; t++) {
        s0[t] = g_stack[(long)t * WELEM + f0];
        s1[t] = g_stack[(long)t * WELEM + f1];
    }
    float w0 = conv_w[f0], w1 = conv_w[f1];

#pragma unroll 4
    for (int b = 0; b < BATCH; b++) {
        float a0 = w0, a1 = w1;
#pragma unroll
        for (int t = 0; t < NT; t++) {
            float al = SCALING * sal[b * NT + t];
            a0 += al * s0[t];
            a1 += al * s1[t];
        }
        *(__half2*)(g_agg + (long)b * WELEM + g0) = __floats2half2_rn(a0, a1);
    }
}

// ---------------------------------------------------------------------------
// Kernel C: fp16 mma.sync m16n8k16 implicit-GEMM conv.
// CTA: M=128 x N=224 (4 rows x 56px) x K=2304 in 36 chunks of 64.
// 512 threads = 16 warps (4m x 4n); warp tile 32x56; n-warp == image row.
// ldmatrix fragments, 4-stage cp.async pipeline, one barrier per chunk.
// ---------------------------------------------------------------------------
#define KC      64
#define NCHUNK  36
#define ASTRB   144                     // A row stride bytes (72 halves)
#define ABYTES  (128 * ASTRB)           // 18432
#define BSTRB   528                     // B ci-row stride bytes (264 halves)
#define BBYTES  (KC * BSTRB)            // 33792
#define STBYTES (ABYTES + BBYTES)       // 52224
#define STAGES  4
#define CONV_SMEM (STAGES * STBYTES)    // 208896

__global__ __launch_bounds__(512, 1)
void conv_mma_kernel(float* __restrict__ out) {
    extern __shared__ uint32_t sm[];
    const uint32_t smb = smem_u32(sm);

    const int tid  = threadIdx.x;
    const int lane = tid & 31;
    const int wid  = tid >> 5;
    const int wm   = wid >> 2;      // m offset wm*32
    const int wn   = wid & 3;       // image row within 4-row tile
    const int q    = lane >> 2;     // 0..7
    const int t4   = lane & 3;      // 0..3

    const int b  = blockIdx.z;
    const int mt = blockIdx.y;      // 0..1
    const int nt = blockIdx.x;      // 0..13
    const int y0 = nt * 4;

    const __half* agg_b = g_agg + (long)b * WELEM + (long)(mt * 128) * KTOT;

    // ldmatrix lane offsets
    const int gA = lane >> 3, rA = lane & 7;
    const uint32_t a_lane = (uint32_t)(((gA & 1) * 8 + rA) * ASTRB + (gA >> 1) * 16);
    const uint32_t b_lane = (uint32_t)((lane & 15) * BSTRB + wn * 128);

    // cp.async thread mapping (A: 1024x16B, B: 2048x16B per chunk)
    const int amA = tid >> 3, asg = tid & 7;   // A: row, 16B seg (x2 iters)

    auto issue = [&](int c, int buf) {
        uint32_t sa = smb + buf * STBYTES;
        // A: 128 rows x 128B
#pragma unroll
        for (int j = 0; j < 2; j++) {
            int m = amA + j * 64;
            cp16(sa + m * ASTRB + asg * 16,
                 agg_b + (long)m * KTOT + c * KC + asg * 8);
        }
        // B: 64 ci x 4 rows x 128B, from kw-shifted padded copy
        int tap = c >> 2;
        int ci0 = (c & 3) * 64;
        int kh = tap / 3, kw = tap % 3;
        const __half* gsrc = g_xpad
            + ((long)(kw * BATCH + b) * CIN + ci0) * PPLANE + (y0 + kh) * PWH;
        uint32_t bb = sa + ABYTES;
#pragma unroll
        for (int j = 0; j < 4; j++) {
            int idx = tid + j * 512;
            int rowid = idx >> 3, e = idx & 7;
            int ci = rowid >> 2, yy = rowid & 3;
            cp16(bb + ci * BSTRB + yy * 128 + e * 16,
                 gsrc + (long)ci * PPLANE + yy * PWH + e * 8);
        }
        asm volatile("cp.async.commit_group;" ::: "memory");
    };

    issue(0, 0);
    issue(1, 1);
    issue(2, 2);

    float acc[2][7][4];
#pragma unroll
    for (int i = 0; i < 2; i++)
#pragma unroll
        for (int j = 0; j < 7; j++)
#pragma unroll
            for (int e = 0; e < 4; e++) acc[i][j][e] = 0.f;

    for (int c = 0; c < NCHUNK; c++) {
        asm volatile("cp.async.wait_group 2;" ::: "memory");
        __syncthreads();

        const int buf = c & 3;
        if (c + 3 < NCHUNK) issue(c + 3, (c + 3) & 3);
        else asm volatile("cp.async.commit_group;" ::: "memory");

        const uint32_t stage = smb + buf * STBYTES;
        const uint32_t aw = stage + (wm * 32) * ASTRB + a_lane;
        const uint32_t bw = stage + ABYTES + b_lane;

#pragma unroll
        for (int ks = 0; ks < 4; ks++) {
            const int kk = ks * 16;
            uint32_t af[2][4];
#pragma unroll
            for (int ms = 0; ms < 2; ms++) {
                asm volatile(
                    "ldmatrix.sync.aligned.m8n8.x4.shared.b16 {%0,%1,%2,%3}, [%4];"
                    : "=r"(af[ms][0]), "=r"(af[ms][1]), "=r"(af[ms][2]), "=r"(af[ms][3])
                    : "r"(aw + ms * (16 * ASTRB) + kk * 2));
            }
            uint32_t bf[7][2];
#pragma unroll
            for (int ns = 0; ns < 7; ns++) {
                asm volatile(
                    "ldmatrix.sync.aligned.m8n8.x2.trans.shared.b16 {%0,%1}, [%2];"
                    : "=r"(bf[ns][0]), "=r"(bf[ns][1])
                    : "r"(bw + kk * BSTRB + ns * 16));
            }
#pragma unroll
            for (int ms = 0; ms < 2; ms++)
#pragma unroll
                for (int ns = 0; ns < 7; ns++) {
                    asm volatile(
                        "mma.sync.aligned.m16n8k16.row.col.f32.f16.f16.f32 "
                        "{%0,%1,%2,%3}, {%4,%5,%6,%7}, {%8,%9}, {%0,%1,%2,%3};"
                        : "+f"(acc[ms][ns][0]), "+f"(acc[ms][ns][1]),
                          "+f"(acc[ms][ns][2]), "+f"(acc[ms][ns][3])
                        : "r"(af[ms][0]), "r"(af[ms][1]), "r"(af[ms][2]), "r"(af[ms][3]),
                          "r"(bf[ns][0]), "r"(bf[ns][1]));
                }
        }
    }

    // ---- epilogue ----
    {
        const int mbase = mt * 128 + wm * 32;
        const int nbase = nt * 224 + wn * 56;
#pragma unroll
        for (int ms = 0; ms < 2; ms++) {
            int row0 = mbase + ms * 16 + q;
#pragma unroll
            for (int ns = 0; ns < 7; ns++) {
                int np = nbase + ns * 8 + t4 * 2;
                *(float2*)(out + ((long)(b * COUT + row0)) * HW + np) =
                    make_float2(acc[ms][ns][0], acc[ms][ns][1]);
                *(float2*)(out + ((long)(b * COUT + row0 + 8)) * HW + np) =
                    make_float2(acc[ms][ns][2], acc[ms][ns][3]);
            }
        }
    }
}

// ---------------------------------------------------------------------------
extern "C" void kernel_launch(void* const* d_in, const int* in_sizes, int n_in,
                              void* d_out, int out_size) {
    const float* x      = (const float*)d_in[0];
    const float* alphas = (const float*)d_in[1];
    const float* conv_w = (const float*)d_in[2];
    const float* lora_A = (const float*)d_in[3];
    const float* lora_B = (const float*)d_in[4];
    float* out = (float*)d_out;

    pad_kernel<<<BATCH * CIN, 256>>>(x);

    dim3 gA(DIM / 128, DIM / 32, NT);
    synth_stack_kernel<<<gA, 256>>>(lora_A, lora_B);

    build_agg_kernel<<<WELEM / 512, 256>>>(alphas, conv_w);

    cudaFuncSetAttribute(conv_mma_kernel,
                         cudaFuncAttributeMaxDynamicSharedMemorySize, CONV_SMEM);
    dim3 gC(14, 2, BATCH);
    conv_mma_kernel<<<gC, 512, CONV_SMEM>>>(out);
}